// round 16
// baseline (speedup 1.0000x reference)
#include <cuda_runtime.h>
#include <math.h>

#define T    65536
#define NCH  32
#define CS   256        // biquad chunk
#define NC   (T/CS)     // 256 chunks
#define ACH  224        // allpass chunk (< min allpass lag 225)
#define NAC  ((T + ACH - 1)/ACH)   // 293
#define CCH  1024       // comb chunk
#define NCC  (T/CCH)    // 64
#define CR2  2048       // comb ring (pow2)
#define ARING 1024
#define SEG   32        // compressor segment length
#define NSEG  (T/SEG)   // 2048
#define MROW  36        // padded pieces per (seg,ch): 33 used

// ------------------------------- scratch -----------------------------------
__device__ float g_buf1[(size_t)NCH*T];              // y [ch][t] -> xc [ch][t] (in place)
__device__ float g_buf2[(size_t)NCH*T];              // reverb out [ch][t]
__device__ float g_buf4[(size_t)NCH*T];              // tgt [ch][t]
__device__ float g_cacc[(size_t)8*NCH*T];            // per-comb output timelines
__device__ float g_maps[(size_t)(NSEG+8)*NCH*MROW];  // segment map intercepts C_k
__device__ float g_e0[(size_t)NSEG*NCH];             // segment boundary states

__device__ float g_coef[NCH][6][5];            // b0 b1 b2 a1 a2
__device__ float g_P[NCH][144];                // A^256
__device__ float g_gin[NCH];
__device__ float g_cmp[NCH][4];                // a_att a_rel thr slope
__device__ float g_K[NCH][33];                 // K_k = aA^k * aR^(32-k)
__device__ float g_vrb[NCH][4];                // fb damp wet1 dryg
__device__ float g_pg[NCH][2];                 // gout*cos gout*sin

// ------------------------------- params ------------------------------------
__device__ void d_shelf(double fc,double g,double s,double*B,double*A){
    const double SR=44100.0, PI=3.14159265358979323846;
    double Aa=pow(10.0,g/40.0), w=2.0*PI*fc/SR, cw=cos(w);
    double al=sin(w)*0.7071067811865476, sq=2.0*sqrt(Aa)*al;
    B[0]=Aa*((Aa+1.0)+s*(Aa-1.0)*cw+sq);
    B[1]=-2.0*s*Aa*((Aa-1.0)+s*(Aa+1.0)*cw);
    B[2]=Aa*((Aa+1.0)+s*(Aa-1.0)*cw-sq);
    A[0]=(Aa+1.0)-s*(Aa-1.0)*cw+sq;
    A[1]=2.0*s*((Aa-1.0)-s*(Aa+1.0)*cw);
    A[2]=(Aa+1.0)-s*(Aa-1.0)*cw-sq;
}
__device__ void d_peak(double fc,double g,double q,double*B,double*A){
    const double SR=44100.0, PI=3.14159265358979323846;
    double Aa=pow(10.0,g/40.0), w=2.0*PI*fc/SR, cw=cos(w), al=sin(w)/(2.0*q);
    B[0]=1.0+al*Aa; B[1]=-2.0*cw; B[2]=1.0-al*Aa;
    A[0]=1.0+al/Aa; A[1]=-2.0*cw; A[2]=1.0-al/Aa;
}

__global__ void k_params(const float* __restrict__ p, float* __restrict__ pout){
    int ch = threadIdx.x; if (ch >= NCH) return;
    const float* pf = p + ch*24;
    const double SR=44100.0, PI=3.14159265358979323846;
    double gin_db=(double)pf[0]*60.0-48.0;
    double hp=(double)pf[1]*350.0, lp=3000.0+(double)pf[2]*19000.0;
    double hsf=1500.0+(double)pf[3]*14500.0, hsg=(double)pf[4]*30.0-15.0;
    double lsf=30.0+(double)pf[5]*420.0,    lsg=(double)pf[6]*30.0-15.0;
    double mhf=600.0+(double)pf[7]*6400.0,  mhg=(double)pf[8]*30.0-15.0, mhq=0.5+(double)pf[9]*2.5;
    double mlf=200.0+(double)pf[10]*2300.0, mlg=(double)pf[11]*30.0-15.0, mlq=0.5+(double)pf[12]*2.5;
    double cth=-20.0+(double)pf[13]*30.0, crt=1.0+(double)pf[14]*19.0;
    double cat=1.0+(double)pf[15]*29.0,   crl=100.0+(double)pf[16]*3900.0;
    double god=(double)pf[22]*60.0-48.0,  pan=0.3+(double)pf[23]*0.4;

    double B[6][3], A[6][3];
    { double K=tan(PI*hp/SR),a1=(K-1.0)/(K+1.0),b0=1.0/(1.0+K);
      B[0][0]=b0;B[0][1]=-b0;B[0][2]=0;A[0][0]=1;A[0][1]=a1;A[0][2]=0; }
    { double K=tan(PI*lp/SR),a1=(K-1.0)/(K+1.0),b0=K/(1.0+K);
      B[1][0]=b0;B[1][1]=b0;B[1][2]=0;A[1][0]=1;A[1][1]=a1;A[1][2]=0; }
    d_shelf(hsf,hsg, 1.0,B[2],A[2]);
    d_shelf(lsf,lsg,-1.0,B[3],A[3]);
    d_peak (mhf,mhg,mhq,B[4],A[4]);
    d_peak (mlf,mlg,mlq,B[5],A[5]);

    double nb[6][3], na[6][2];
    for (int s=0;s<6;s++){
        double a0=A[s][0];
        float b0=(float)(B[s][0]/a0),b1=(float)(B[s][1]/a0),b2=(float)(B[s][2]/a0);
        float a1=(float)(A[s][1]/a0),a2=(float)(A[s][2]/a0);
        g_coef[ch][s][0]=b0;g_coef[ch][s][1]=b1;g_coef[ch][s][2]=b2;
        g_coef[ch][s][3]=a1;g_coef[ch][s][4]=a2;
        nb[s][0]=b0;nb[s][1]=b1;nb[s][2]=b2;na[s][0]=a1;na[s][1]=a2;
    }
    // one-step 12x12 state map via unit vectors (input = 0)
    float M[144], Tm[144];
    for (int k=0;k<12;k++){
        double z[12]; for(int i=0;i<12;i++) z[i]=0.0; z[k]=1.0;
        double s=0.0;
        for (int sc=0;sc<6;sc++){
            double y =nb[sc][0]*s+z[2*sc];
            double z1=nb[sc][1]*s-na[sc][0]*y+z[2*sc+1];
            double z2=nb[sc][2]*s-na[sc][1]*y;
            z[2*sc]=z1; z[2*sc+1]=z2; s=y;
        }
        for (int r=0;r<12;r++) M[r*12+k]=(float)z[r];
    }
    for (int it=0; it<8; it++){       // M = M^2, 8x -> A^256
        for (int r=0;r<12;r++) for(int c=0;c<12;c++){
            float acc=0.f;
            for (int k=0;k<12;k++) acc=fmaf(M[r*12+k],M[k*12+c],acc);
            Tm[r*12+c]=acc;
        }
        for (int i=0;i<144;i++) M[i]=Tm[i];
    }
    for (int i=0;i<144;i++) g_P[ch][i]=M[i];

    g_gin[ch]=(float)pow(10.0,gin_db/20.0);
    double aat=exp(-1.0/(cat*0.001*SR)), arl=exp(-1.0/(crl*0.001*SR));
    g_cmp[ch][0]=(float)aat;
    g_cmp[ch][1]=(float)arl;
    g_cmp[ch][2]=(float)cth;
    g_cmp[ch][3]=(float)(1.0-1.0/crt);
    for (int k=0;k<=32;k++)
        g_K[ch][k]=(float)(pow(aat,(double)k)*pow(arl,(double)(32-k)));

    g_vrb[ch][0]=(float)((double)pf[17]*0.28+0.7);
    g_vrb[ch][1]=(float)((double)pf[18]*0.4);
    g_vrb[ch][2]=(float)(3.0*(double)pf[19]*0.5*(1.0+(double)pf[21]));
    g_vrb[ch][3]=(float)(2.0*(double)pf[20]);

    double gol=pow(10.0,god/20.0), th=pan*PI*0.5;
    g_pg[ch][0]=(float)(gol*cos(th));
    g_pg[ch][1]=(float)(gol*sin(th));

    if (pout){
        float* po=pout+ch*24;
        po[0]=(float)gin_db; po[1]=(float)hp; po[2]=(float)lp; po[3]=(float)hsf;
        po[4]=(float)hsg; po[5]=(float)lsf; po[6]=(float)lsg; po[7]=(float)mhf;
        po[8]=(float)mhg; po[9]=(float)mhq; po[10]=(float)mlf; po[11]=(float)mlg;
        po[12]=(float)mlq; po[13]=(float)cth; po[14]=(float)crt; po[15]=(float)cat;
        po[16]=(float)crl; po[17]=pf[17]; po[18]=pf[18]; po[19]=pf[19];
        po[20]=pf[20]; po[21]=pf[21]; po[22]=(float)god; po[23]=(float)pan;
    }
}

// --------------------------- biquad blocked scan ----------------------------
__device__ __forceinline__ float bq6(float s, float z[12], const float c[6][5]){
#pragma unroll
    for (int k=0;k<6;k++){
        float y  = fmaf(c[k][0], s, z[2*k]);
        float z1 = fmaf(c[k][1], s, z[2*k+1]) - c[k][3]*y;
        z[2*k+1] = fmaf(c[k][2], s, -(c[k][4]*y));
        z[2*k]   = z1;
        s = y;
    }
    return s;
}

__global__ void __launch_bounds__(256) k_biquad(const float* __restrict__ x){
    __shared__ float sF[NC][12];
    __shared__ float sI[NC][12];
    int ch = blockIdx.x, tid = threadIdx.x;
    float c[6][5];
#pragma unroll
    for (int k=0;k<6;k++)
#pragma unroll
        for (int j=0;j<5;j++) c[k][j]=g_coef[ch][k][j];
    float gin = g_gin[ch];
    float thr = g_cmp[ch][2], slope = g_cmp[ch][3];
    const float4* xc = (const float4*)(x + (size_t)ch*T) + tid*(CS/4);

    float z[12];
#pragma unroll
    for (int i=0;i<12;i++) z[i]=0.f;
    for (int i=0;i<CS/4;i++){
        float4 v = xc[i];
        bq6(v.x*gin,z,c); bq6(v.y*gin,z,c); bq6(v.z*gin,z,c); bq6(v.w*gin,z,c);
    }
#pragma unroll
    for (int i=0;i<12;i++) sF[tid][i]=z[i];
    __syncthreads();

    if (tid < 12){
        int r = tid;
        float Pr[12];
#pragma unroll
        for (int k=0;k<12;k++) Pr[k]=g_P[ch][r*12+k];
        sI[0][r]=0.f;
        __syncwarp(0xFFFu);
        for (int j=0;j<NC-1;j++){
            float acc = sF[j][r];
#pragma unroll
            for (int k=0;k<12;k++) acc = fmaf(Pr[k], sI[j][k], acc);
            __syncwarp(0xFFFu);
            sI[j+1][r]=acc;
            __syncwarp(0xFFFu);
        }
    }
    __syncthreads();

#pragma unroll
    for (int i=0;i<12;i++) z[i]=sI[tid][i];
    int t0 = tid*CS;
    float* yb = g_buf1 + (size_t)ch*T + t0;
    float* tb = g_buf4 + (size_t)ch*T + t0;
    for (int i=0;i<CS/4;i++){
        float4 v = xc[i];
        float y0=bq6(v.x*gin,z,c), y1=bq6(v.y*gin,z,c);
        float y2=bq6(v.z*gin,z,c), y3=bq6(v.w*gin,z,c);
        ((float4*)yb)[i] = make_float4(y0,y1,y2,y3);
        float ys[4], tg[4];
        ys[0]=y0; ys[1]=y1; ys[2]=y2; ys[3]=y3;
#pragma unroll
        for (int q=0;q<4;q++){
            float lvl = __log2f(fabsf(ys[q]) + 1e-6f) * 6.0205999132796239f;
            tg[q] = fminf(0.f, (thr - lvl)*slope);
        }
        ((float4*)tb)[i] = make_float4(tg[0],tg[1],tg[2],tg[3]);
    }
}

// ============== compressor: EXACT min-affine segment decomposition ==========
// step: e' = min(aA*e + d, aR*e + d)   (aA < aR => min selects attack/release
// exactly).  32-step segment map: h(e) = min_{k=0..32}(K_k*e + C_k),
// K_k = aA^k aR^(32-k), C_k by triangular DP.

// Phase A: build maps. Block = 8 warps = 8 segments; smem tile transposes
// tgt from [ch][t] (conflict-free stride 257).
__global__ void __launch_bounds__(256) k_cmapA(){
    __shared__ float smT[32*257];
    int tid = threadIdx.x, blk = blockIdx.x;
    int ch = tid & 31, w = tid >> 5;
    int s  = blk*8 + w;

    // load 32ch x 257t tile (coalesced per row)
    for (int r=0;r<32;r++){
        int gt = blk*256 + tid;
        smT[r*257 + tid] = g_buf4[(size_t)r*T + gt];   // blk*256+255 <= T-1
        if (tid == 0){
            int g2 = blk*256 + 256;
            smT[r*257 + 256] = (g2 < T) ? g_buf4[(size_t)r*T + g2] : 0.f;
        }
    }
    __syncthreads();

    float aA = g_cmp[ch][0], aR = g_cmp[ch][1];
    int base = w*32;
    float C[33];
    C[0] = 0.f;
    float T0 = smT[ch*257 + base];
#pragma unroll
    for (int t=0;t<SEG;t++){
        float T1 = smT[ch*257 + base + t + 1];
        float d = T0 - T1;
#pragma unroll
        for (int k=SEG;k>=1;k--){
            if (k == t+1)      C[k] = fmaf(aA, C[k-1], d);
            else if (k <= t)   C[k] = fminf(fmaf(aA, C[k-1], d), fmaf(aR, C[k], d));
        }
        C[0] = fmaf(aR, C[0], d);
        T0 = T1;
    }
    float* o = g_maps + ((size_t)s*NCH + ch)*MROW;
#pragma unroll
    for (int k=0;k<33;k++) o[k] = C[k];
}

// min over 33 candidates, tree depth 6
__device__ __forceinline__ float min33(float* v){
#pragma unroll
    for (int i=0;i<16;i++) v[i] = fminf(v[i], v[i+16]);
#pragma unroll
    for (int i=0;i<8;i++)  v[i] = fminf(v[i], v[i+8]);
#pragma unroll
    for (int i=0;i<4;i++)  v[i] = fminf(v[i], v[i+4]);
    v[0] = fminf(v[0], v[2]); v[1] = fminf(v[1], v[3]);
    return fminf(fminf(v[0], v[1]), v[32]);
}

// Phase B: serial boundary pass (1 warp, lane = channel), 4-deep prefetch
__global__ void __launch_bounds__(32) k_cmapB(){
    int ch = threadIdx.x;
    float K[33];
#pragma unroll
    for (int k=0;k<33;k++) K[k] = g_K[ch][k];
    const float* __restrict__ mp = g_maps;
    float* __restrict__ e0 = g_e0;
    float e = -g_buf4[(size_t)ch*T];     // e_{-1} = -tgt[0]

    float4 b0[9], b1[9], b2[9], b3[9];
    size_t row = (size_t)ch*MROW;
#pragma unroll
    for (int j=0;j<9;j++){
        b0[j] = *(const float4*)(mp + ((size_t)0*NCH*MROW) + row + 4*j);
        b1[j] = *(const float4*)(mp + ((size_t)1*NCH*MROW) + row + 4*j);
        b2[j] = *(const float4*)(mp + ((size_t)2*NCH*MROW) + row + 4*j);
    }
    for (int s=0; s<NSEG; s+=4){
        float cand[33];
#pragma unroll
        for (int j=0;j<9;j++) b3[j] = *(const float4*)(mp + ((size_t)(s+3)*NCH*MROW) + row + 4*j);
        e0[(size_t)s*32 + ch] = e;
#pragma unroll
        for (int k=0;k<33;k++) cand[k] = fmaf(K[k], e, ((const float*)b0)[k]);
        e = min33(cand);
#pragma unroll
        for (int j=0;j<9;j++) b0[j] = *(const float4*)(mp + ((size_t)(s+4)*NCH*MROW) + row + 4*j);
        e0[(size_t)(s+1)*32 + ch] = e;
#pragma unroll
        for (int k=0;k<33;k++) cand[k] = fmaf(K[k], e, ((const float*)b1)[k]);
        e = min33(cand);
#pragma unroll
        for (int j=0;j<9;j++) b1[j] = *(const float4*)(mp + ((size_t)(s+5)*NCH*MROW) + row + 4*j);
        e0[(size_t)(s+2)*32 + ch] = e;
#pragma unroll
        for (int k=0;k<33;k++) cand[k] = fmaf(K[k], e, ((const float*)b2)[k]);
        e = min33(cand);
#pragma unroll
        for (int j=0;j<9;j++) b2[j] = *(const float4*)(mp + ((size_t)(s+6)*NCH*MROW) + row + 4*j);
        e0[(size_t)(s+3)*32 + ch] = e;
#pragma unroll
        for (int k=0;k<33;k++) cand[k] = fmaf(K[k], e, ((const float*)b3)[k]);
        e = min33(cand);
    }
}

// Phase C: exact within-segment rerun + gain application (fused transposes).
// Block = 8 warps = 8 segments; tiles for tgt and y in dynamic smem.
__global__ void __launch_bounds__(256) k_cmapC(){
    extern __shared__ float sm[];
    float* smT = sm;              // 32 x 257
    float* smY = sm + 32*257;     // 32 x 257 (256 used)
    int tid = threadIdx.x, blk = blockIdx.x;
    int ch = tid & 31, w = tid >> 5;
    int s  = blk*8 + w;

    for (int r=0;r<32;r++){
        int gt = blk*256 + tid;
        smT[r*257 + tid] = g_buf4[(size_t)r*T + gt];
        smY[r*257 + tid] = g_buf1[(size_t)r*T + gt];
        if (tid == 0){
            int g2 = blk*256 + 256;
            smT[r*257 + 256] = (g2 < T) ? g_buf4[(size_t)r*T + g2] : 0.f;
        }
    }
    __syncthreads();

    float aA = g_cmp[ch][0], aR = g_cmp[ch][1];
    const float K2 = 0.16609640474436813f; // log2(10)/20
    float e = g_e0[(size_t)s*32 + ch];
    int base = w*32;
    float T0 = smT[ch*257 + base];
#pragma unroll
    for (int i=0;i<SEG;i++){
        float T1 = smT[ch*257 + base + i + 1];
        float d = T0 - T1;
        e = fminf(fmaf(aA, e, d), fmaf(aR, e, d));
        float g = e + T1;
        smY[ch*257 + base + i] *= exp2f(g*K2);
        T0 = T1;
    }
    __syncthreads();

    for (int r=0;r<32;r++){
        int gt = blk*256 + tid;
        g_buf1[(size_t)r*T + gt] = smY[r*257 + tid];
    }
}

// --------------- combs: one block per (channel, comb), shuffle scan ----------
// s_t = damp*s_{t-1} + (1-damp)*w[t-L] ; w[t] = inp + fb*s_t ; out = w[t-L]
// 4-step decayed shuffle scan = exact 16-tap window (damp<=0.4 -> 4e-7);
// cross-warp seeds via unseeded warp finals (damp^32 ~ 2e-13).
__global__ void __launch_bounds__(CCH) k_comb(){
    __shared__ float ring[CR2];
    __shared__ float fin[32];
    __shared__ float carry;
    const int Lc[8] = {1116,1188,1277,1356,1422,1491,1557,1617};

    int ch = blockIdx.x & 31, k = blockIdx.x >> 5;
    int L = Lc[k];
    int tid = threadIdx.x, lane = tid & 31, w = tid >> 5;
    for (int i = tid; i < CR2; i += CCH) ring[i] = 0.f;
    if (tid == 0) carry = 0.f;
    __syncthreads();

    float fb = g_vrb[ch][0], damp = g_vrb[ch][1];
    float omd = 1.f - damp;
    float d1 = damp, d2 = d1*d1, d4 = d2*d2, d8 = d4*d4;
    float dl = powf(damp, (float)(lane+1));
    const float* __restrict__ xb = g_buf1 + (size_t)ch*T;
    float* __restrict__ co = g_cacc + ((size_t)k*NCH + ch)*T;

    for (int c = 0; c < NCC; c++){
        int t = c*CCH + tid;
        float inp = 0.015f * xb[t];
        float wv = ring[(t - L) & (CR2-1)];
        float sv = omd * wv;
        float v;
        v = __shfl_up_sync(0xFFFFFFFFu, sv, 1); if (lane >= 1) sv = fmaf(d1, v, sv);
        v = __shfl_up_sync(0xFFFFFFFFu, sv, 2); if (lane >= 2) sv = fmaf(d2, v, sv);
        v = __shfl_up_sync(0xFFFFFFFFu, sv, 4); if (lane >= 4) sv = fmaf(d4, v, sv);
        v = __shfl_up_sync(0xFFFFFFFFu, sv, 8); if (lane >= 8) sv = fmaf(d8, v, sv);
        if (lane == 31) fin[w] = sv;
        float seed0 = carry;
        co[t] = wv;
        __syncthreads();
        float seed = (w == 0) ? seed0 : fin[w-1];
        sv = fmaf(dl, seed, sv);
        ring[t & (CR2-1)] = fmaf(fb, sv, inp);
        if (tid == CCH-1) carry = sv;
        __syncthreads();
    }
}

// ----------------- allpass chain (sums 8 comb streams) + out -----------------
__global__ void __launch_bounds__(ACH) k_ap(){
    __shared__ float ring[4*ARING];
    const int La[4] = {556,441,341,225};
    int ch = blockIdx.x, tid = threadIdx.x;
    for (int i = tid; i < 4*ARING; i += ACH) ring[i] = 0.f;
    __syncthreads();

    float wet1 = g_vrb[ch][2], dryg = g_vrb[ch][3];
    const float* __restrict__ xb = g_buf1 + (size_t)ch*T;
    float* __restrict__ ob       = g_buf2 + (size_t)ch*T;

    float cur[8], curx;
#pragma unroll
    for (int k=0;k<8;k++) cur[k] = g_cacc[((size_t)k*NCH + ch)*T + tid];
    curx = xb[tid];

    for (int c = 0; c < NAC; c++){
        int t = c*ACH + tid;
        int tn = t + ACH;
        float nxt[8], nx;
#pragma unroll
        for (int k=0;k<8;k++) nxt[k] = (tn < T) ? g_cacc[((size_t)k*NCH + ch)*T + tn] : 0.f;
        nx = (tn < T) ? xb[tn] : 0.f;
        if (t < T){
            float a = ((cur[0]+cur[1])+(cur[2]+cur[3])) + ((cur[4]+cur[5])+(cur[6]+cur[7]));
#pragma unroll
            for (int k=0;k<4;k++){
                float bufv = ring[k*ARING + ((t - La[k]) & (ARING-1))];
                ring[k*ARING + (t & (ARING-1))] = fmaf(bufv, 0.5f, a);
                a = bufv - a;
            }
            ob[t] = a*wet1 + curx*dryg;
        }
#pragma unroll
        for (int k=0;k<8;k++) cur[k] = nxt[k];
        curx = nx;
        __syncthreads();
    }
}

// --------------------------------- mix -------------------------------------
__global__ void k_mix(float* __restrict__ out){
    int idx = blockIdx.x*blockDim.x + threadIdx.x;   // over 4*T
    if (idx >= 4*T) return;
    int b = idx / T, t = idx - b*T;
    float l=0.f, r=0.f;
#pragma unroll
    for (int n=0;n<8;n++){
        int ch = b*8 + n;
        float v = g_buf2[(size_t)ch*T + t];
        l = fmaf(v, g_pg[ch][0], l);
        r = fmaf(v, g_pg[ch][1], r);
    }
    out[((size_t)(b*2+0))*T + t] = l;
    out[((size_t)(b*2+1))*T + t] = r;
}

// -------------------------------- launch ------------------------------------
#define CMAPC_SM (2*32*257*4)

extern "C" void kernel_launch(void* const* d_in, const int* in_sizes, int n_in,
                              void* d_out, int out_size){
    const float* x = (const float*)d_in[0];
    const float* p = (const float*)d_in[1];
    if (n_in >= 2 && in_sizes[0] < in_sizes[1]) {
        const float* tmp = x; x = p; p = tmp;
    }
    float* out  = (float*)d_out;
    float* pout = (out_size >= 4*2*T + 4*8*24) ? out + (size_t)4*2*T : nullptr;

    static int smem_set = 0;
    if (!smem_set){
        cudaFuncSetAttribute(k_cmapC, cudaFuncAttributeMaxDynamicSharedMemorySize, CMAPC_SM);
        smem_set = 1;
    }

    k_params<<<1, 32>>>(p, pout);
    k_biquad<<<NCH, 256>>>(x);
    k_cmapA<<<NSEG/8, 256>>>();
    k_cmapB<<<1, 32>>>();
    k_cmapC<<<NSEG/8, 256, CMAPC_SM>>>();
    k_comb<<<8*NCH, CCH>>>();
    k_ap<<<NCH, ACH>>>();
    k_mix<<<(4*T + 255)/256, 256>>>(out);
}

// round 17
// speedup vs baseline: 1.0129x; 1.0129x over previous
#include <cuda_runtime.h>
#include <math.h>

#define T    65536
#define NCH  32
#define CS   256        // biquad chunk
#define NC   (T/CS)     // 256 chunks
#define ACH  224        // allpass chunk (< min allpass lag 225)
#define NAC  ((T + ACH - 1)/ACH)   // 293
#define CCH  1024       // comb chunk
#define NCC  (T/CCH)    // 64
#define CR2  2048       // comb ring (pow2)
#define ARING 1024
#define SEG   32        // compressor segment length
#define NSEG  (T/SEG)   // 2048
#define MROW  36        // padded pieces per (seg,ch): 33 used

// ------------------------------- scratch -----------------------------------
__device__ float g_buf1[(size_t)NCH*T];              // y [ch][t] -> xc [ch][t] (in place)
__device__ float g_buf2[(size_t)NCH*T];              // reverb out [ch][t]
__device__ float g_buf4[(size_t)NCH*T];              // tgt [ch][t]
__device__ float g_cacc[(size_t)8*NCH*T];            // per-comb output timelines
__device__ float g_maps[(size_t)(NSEG+8)*NCH*MROW];  // segment map intercepts C_k
__device__ float g_e0[(size_t)NSEG*NCH];             // segment boundary states

__device__ float g_coef[NCH][6][5];            // b0 b1 b2 a1 a2
__device__ float g_P[NCH][144];                // A^256
__device__ float g_gin[NCH];
__device__ float g_cmp[NCH][4];                // a_att a_rel thr slope
__device__ float g_K[NCH][33];                 // K_k = aA^k * aR^(32-k)
__device__ float g_vrb[NCH][4];                // fb damp wet1 dryg
__device__ float g_pg[NCH][2];                 // gout*cos gout*sin

// ------------------------------- params ------------------------------------
__device__ void d_shelf(double fc,double g,double s,double*B,double*A){
    const double SR=44100.0, PI=3.14159265358979323846;
    double Aa=pow(10.0,g/40.0), w=2.0*PI*fc/SR, cw=cos(w);
    double al=sin(w)*0.7071067811865476, sq=2.0*sqrt(Aa)*al;
    B[0]=Aa*((Aa+1.0)+s*(Aa-1.0)*cw+sq);
    B[1]=-2.0*s*Aa*((Aa-1.0)+s*(Aa+1.0)*cw);
    B[2]=Aa*((Aa+1.0)+s*(Aa-1.0)*cw-sq);
    A[0]=(Aa+1.0)-s*(Aa-1.0)*cw+sq;
    A[1]=2.0*s*((Aa-1.0)-s*(Aa+1.0)*cw);
    A[2]=(Aa+1.0)-s*(Aa-1.0)*cw-sq;
}
__device__ void d_peak(double fc,double g,double q,double*B,double*A){
    const double SR=44100.0, PI=3.14159265358979323846;
    double Aa=pow(10.0,g/40.0), w=2.0*PI*fc/SR, cw=cos(w), al=sin(w)/(2.0*q);
    B[0]=1.0+al*Aa; B[1]=-2.0*cw; B[2]=1.0-al*Aa;
    A[0]=1.0+al/Aa; A[1]=-2.0*cw; A[2]=1.0-al/Aa;
}

__global__ void k_params(const float* __restrict__ p, float* __restrict__ pout){
    int ch = threadIdx.x; if (ch >= NCH) return;
    const float* pf = p + ch*24;
    const double SR=44100.0, PI=3.14159265358979323846;
    double gin_db=(double)pf[0]*60.0-48.0;
    double hp=(double)pf[1]*350.0, lp=3000.0+(double)pf[2]*19000.0;
    double hsf=1500.0+(double)pf[3]*14500.0, hsg=(double)pf[4]*30.0-15.0;
    double lsf=30.0+(double)pf[5]*420.0,    lsg=(double)pf[6]*30.0-15.0;
    double mhf=600.0+(double)pf[7]*6400.0,  mhg=(double)pf[8]*30.0-15.0, mhq=0.5+(double)pf[9]*2.5;
    double mlf=200.0+(double)pf[10]*2300.0, mlg=(double)pf[11]*30.0-15.0, mlq=0.5+(double)pf[12]*2.5;
    double cth=-20.0+(double)pf[13]*30.0, crt=1.0+(double)pf[14]*19.0;
    double cat=1.0+(double)pf[15]*29.0,   crl=100.0+(double)pf[16]*3900.0;
    double god=(double)pf[22]*60.0-48.0,  pan=0.3+(double)pf[23]*0.4;

    double B[6][3], A[6][3];
    { double K=tan(PI*hp/SR),a1=(K-1.0)/(K+1.0),b0=1.0/(1.0+K);
      B[0][0]=b0;B[0][1]=-b0;B[0][2]=0;A[0][0]=1;A[0][1]=a1;A[0][2]=0; }
    { double K=tan(PI*lp/SR),a1=(K-1.0)/(K+1.0),b0=K/(1.0+K);
      B[1][0]=b0;B[1][1]=b0;B[1][2]=0;A[1][0]=1;A[1][1]=a1;A[1][2]=0; }
    d_shelf(hsf,hsg, 1.0,B[2],A[2]);
    d_shelf(lsf,lsg,-1.0,B[3],A[3]);
    d_peak (mhf,mhg,mhq,B[4],A[4]);
    d_peak (mlf,mlg,mlq,B[5],A[5]);

    double nb[6][3], na[6][2];
    for (int s=0;s<6;s++){
        double a0=A[s][0];
        float b0=(float)(B[s][0]/a0),b1=(float)(B[s][1]/a0),b2=(float)(B[s][2]/a0);
        float a1=(float)(A[s][1]/a0),a2=(float)(A[s][2]/a0);
        g_coef[ch][s][0]=b0;g_coef[ch][s][1]=b1;g_coef[ch][s][2]=b2;
        g_coef[ch][s][3]=a1;g_coef[ch][s][4]=a2;
        nb[s][0]=b0;nb[s][1]=b1;nb[s][2]=b2;na[s][0]=a1;na[s][1]=a2;
    }
    // one-step 12x12 state map via unit vectors (input = 0)
    float M[144], Tm[144];
    for (int k=0;k<12;k++){
        double z[12]; for(int i=0;i<12;i++) z[i]=0.0; z[k]=1.0;
        double s=0.0;
        for (int sc=0;sc<6;sc++){
            double y =nb[sc][0]*s+z[2*sc];
            double z1=nb[sc][1]*s-na[sc][0]*y+z[2*sc+1];
            double z2=nb[sc][2]*s-na[sc][1]*y;
            z[2*sc]=z1; z[2*sc+1]=z2; s=y;
        }
        for (int r=0;r<12;r++) M[r*12+k]=(float)z[r];
    }
    for (int it=0; it<8; it++){       // M = M^2, 8x -> A^256
        for (int r=0;r<12;r++) for(int c=0;c<12;c++){
            float acc=0.f;
            for (int k=0;k<12;k++) acc=fmaf(M[r*12+k],M[k*12+c],acc);
            Tm[r*12+c]=acc;
        }
        for (int i=0;i<144;i++) M[i]=Tm[i];
    }
    for (int i=0;i<144;i++) g_P[ch][i]=M[i];

    g_gin[ch]=(float)pow(10.0,gin_db/20.0);
    double aat=exp(-1.0/(cat*0.001*SR)), arl=exp(-1.0/(crl*0.001*SR));
    g_cmp[ch][0]=(float)aat;
    g_cmp[ch][1]=(float)arl;
    g_cmp[ch][2]=(float)cth;
    g_cmp[ch][3]=(float)(1.0-1.0/crt);
    for (int k=0;k<=32;k++)
        g_K[ch][k]=(float)(pow(aat,(double)k)*pow(arl,(double)(32-k)));

    g_vrb[ch][0]=(float)((double)pf[17]*0.28+0.7);
    g_vrb[ch][1]=(float)((double)pf[18]*0.4);
    g_vrb[ch][2]=(float)(3.0*(double)pf[19]*0.5*(1.0+(double)pf[21]));
    g_vrb[ch][3]=(float)(2.0*(double)pf[20]);

    double gol=pow(10.0,god/20.0), th=pan*PI*0.5;
    g_pg[ch][0]=(float)(gol*cos(th));
    g_pg[ch][1]=(float)(gol*sin(th));

    if (pout){
        float* po=pout+ch*24;
        po[0]=(float)gin_db; po[1]=(float)hp; po[2]=(float)lp; po[3]=(float)hsf;
        po[4]=(float)hsg; po[5]=(float)lsf; po[6]=(float)lsg; po[7]=(float)mhf;
        po[8]=(float)mhg; po[9]=(float)mhq; po[10]=(float)mlf; po[11]=(float)mlg;
        po[12]=(float)mlq; po[13]=(float)cth; po[14]=(float)crt; po[15]=(float)cat;
        po[16]=(float)crl; po[17]=pf[17]; po[18]=pf[18]; po[19]=pf[19];
        po[20]=pf[20]; po[21]=pf[21]; po[22]=(float)god; po[23]=(float)pan;
    }
}

// --------------------------- biquad blocked scan ----------------------------
__device__ __forceinline__ float bq6(float s, float z[12], const float c[6][5]){
#pragma unroll
    for (int k=0;k<6;k++){
        float y  = fmaf(c[k][0], s, z[2*k]);
        float z1 = fmaf(c[k][1], s, z[2*k+1]) - c[k][3]*y;
        z[2*k+1] = fmaf(c[k][2], s, -(c[k][4]*y));
        z[2*k]   = z1;
        s = y;
    }
    return s;
}

__global__ void __launch_bounds__(256) k_biquad(const float* __restrict__ x){
    __shared__ float sF[NC][12];
    __shared__ float sI[NC][12];
    int ch = blockIdx.x, tid = threadIdx.x;
    float c[6][5];
#pragma unroll
    for (int k=0;k<6;k++)
#pragma unroll
        for (int j=0;j<5;j++) c[k][j]=g_coef[ch][k][j];
    float gin = g_gin[ch];
    float thr = g_cmp[ch][2], slope = g_cmp[ch][3];
    const float4* xc = (const float4*)(x + (size_t)ch*T) + tid*(CS/4);

    float z[12];
#pragma unroll
    for (int i=0;i<12;i++) z[i]=0.f;
    for (int i=0;i<CS/4;i++){
        float4 v = xc[i];
        bq6(v.x*gin,z,c); bq6(v.y*gin,z,c); bq6(v.z*gin,z,c); bq6(v.w*gin,z,c);
    }
#pragma unroll
    for (int i=0;i<12;i++) sF[tid][i]=z[i];
    __syncthreads();

    if (tid < 12){
        int r = tid;
        float Pr[12];
#pragma unroll
        for (int k=0;k<12;k++) Pr[k]=g_P[ch][r*12+k];
        sI[0][r]=0.f;
        __syncwarp(0xFFFu);
        for (int j=0;j<NC-1;j++){
            float acc = sF[j][r];
#pragma unroll
            for (int k=0;k<12;k++) acc = fmaf(Pr[k], sI[j][k], acc);
            __syncwarp(0xFFFu);
            sI[j+1][r]=acc;
            __syncwarp(0xFFFu);
        }
    }
    __syncthreads();

#pragma unroll
    for (int i=0;i<12;i++) z[i]=sI[tid][i];
    int t0 = tid*CS;
    float* yb = g_buf1 + (size_t)ch*T + t0;
    float* tb = g_buf4 + (size_t)ch*T + t0;
    for (int i=0;i<CS/4;i++){
        float4 v = xc[i];
        float y0=bq6(v.x*gin,z,c), y1=bq6(v.y*gin,z,c);
        float y2=bq6(v.z*gin,z,c), y3=bq6(v.w*gin,z,c);
        ((float4*)yb)[i] = make_float4(y0,y1,y2,y3);
        float ys[4], tg[4];
        ys[0]=y0; ys[1]=y1; ys[2]=y2; ys[3]=y3;
#pragma unroll
        for (int q=0;q<4;q++){
            float lvl = __log2f(fabsf(ys[q]) + 1e-6f) * 6.0205999132796239f;
            tg[q] = fminf(0.f, (thr - lvl)*slope);
        }
        ((float4*)tb)[i] = make_float4(tg[0],tg[1],tg[2],tg[3]);
    }
}

// ============== compressor: EXACT min-affine segment decomposition ==========
// step: e' = min(aA*e + d, aR*e + d)   (aA < aR => min selects attack/release
// exactly).  32-step segment map: h(e) = min_{k=0..32}(K_k*e + C_k),
// K_k = aA^k aR^(32-k), C_k by triangular DP.

// Phase A: build maps. Block = 8 warps = 8 segments; smem tile transposes
// tgt from [ch][t] (conflict-free stride 257).
__global__ void __launch_bounds__(256) k_cmapA(){
    __shared__ float smT[32*257];
    int tid = threadIdx.x, blk = blockIdx.x;
    int ch = tid & 31, w = tid >> 5;
    int s  = blk*8 + w;

    // load 32ch x 257t tile (coalesced per row)
    for (int r=0;r<32;r++){
        int gt = blk*256 + tid;
        smT[r*257 + tid] = g_buf4[(size_t)r*T + gt];   // blk*256+255 <= T-1
        if (tid == 0){
            int g2 = blk*256 + 256;
            smT[r*257 + 256] = (g2 < T) ? g_buf4[(size_t)r*T + g2] : 0.f;
        }
    }
    __syncthreads();

    float aA = g_cmp[ch][0], aR = g_cmp[ch][1];
    int base = w*32;
    float C[33];
    C[0] = 0.f;
    float T0 = smT[ch*257 + base];
#pragma unroll
    for (int t=0;t<SEG;t++){
        float T1 = smT[ch*257 + base + t + 1];
        float d = T0 - T1;
#pragma unroll
        for (int k=SEG;k>=1;k--){
            if (k == t+1)      C[k] = fmaf(aA, C[k-1], d);
            else if (k <= t)   C[k] = fminf(fmaf(aA, C[k-1], d), fmaf(aR, C[k], d));
        }
        C[0] = fmaf(aR, C[0], d);
        T0 = T1;
    }
    float* o = g_maps + ((size_t)s*NCH + ch)*MROW;
#pragma unroll
    for (int k=0;k<33;k++) o[k] = C[k];
}

// min over 33 candidates, tree depth 6
__device__ __forceinline__ float min33(float* v){
#pragma unroll
    for (int i=0;i<16;i++) v[i] = fminf(v[i], v[i+16]);
#pragma unroll
    for (int i=0;i<8;i++)  v[i] = fminf(v[i], v[i+8]);
#pragma unroll
    for (int i=0;i<4;i++)  v[i] = fminf(v[i], v[i+4]);
    v[0] = fminf(v[0], v[2]); v[1] = fminf(v[1], v[3]);
    return fminf(fminf(v[0], v[1]), v[32]);
}

// Phase B: serial boundary pass (1 warp, lane = channel), 4-deep prefetch
__global__ void __launch_bounds__(32) k_cmapB(){
    int ch = threadIdx.x;
    float K[33];
#pragma unroll
    for (int k=0;k<33;k++) K[k] = g_K[ch][k];
    const float* __restrict__ mp = g_maps;
    float* __restrict__ e0 = g_e0;
    float e = -g_buf4[(size_t)ch*T];     // e_{-1} = -tgt[0]

    float4 b0[9], b1[9], b2[9], b3[9];
    size_t row = (size_t)ch*MROW;
#pragma unroll
    for (int j=0;j<9;j++){
        b0[j] = *(const float4*)(mp + ((size_t)0*NCH*MROW) + row + 4*j);
        b1[j] = *(const float4*)(mp + ((size_t)1*NCH*MROW) + row + 4*j);
        b2[j] = *(const float4*)(mp + ((size_t)2*NCH*MROW) + row + 4*j);
    }
    for (int s=0; s<NSEG; s+=4){
        float cand[33];
#pragma unroll
        for (int j=0;j<9;j++) b3[j] = *(const float4*)(mp + ((size_t)(s+3)*NCH*MROW) + row + 4*j);
        e0[(size_t)s*32 + ch] = e;
#pragma unroll
        for (int k=0;k<33;k++) cand[k] = fmaf(K[k], e, ((const float*)b0)[k]);
        e = min33(cand);
#pragma unroll
        for (int j=0;j<9;j++) b0[j] = *(const float4*)(mp + ((size_t)(s+4)*NCH*MROW) + row + 4*j);
        e0[(size_t)(s+1)*32 + ch] = e;
#pragma unroll
        for (int k=0;k<33;k++) cand[k] = fmaf(K[k], e, ((const float*)b1)[k]);
        e = min33(cand);
#pragma unroll
        for (int j=0;j<9;j++) b1[j] = *(const float4*)(mp + ((size_t)(s+5)*NCH*MROW) + row + 4*j);
        e0[(size_t)(s+2)*32 + ch] = e;
#pragma unroll
        for (int k=0;k<33;k++) cand[k] = fmaf(K[k], e, ((const float*)b2)[k]);
        e = min33(cand);
#pragma unroll
        for (int j=0;j<9;j++) b2[j] = *(const float4*)(mp + ((size_t)(s+6)*NCH*MROW) + row + 4*j);
        e0[(size_t)(s+3)*32 + ch] = e;
#pragma unroll
        for (int k=0;k<33;k++) cand[k] = fmaf(K[k], e, ((const float*)b3)[k]);
        e = min33(cand);
    }
}

// Phase C: exact within-segment rerun + gain application (fused transposes).
// Block = 8 warps = 8 segments; tiles for tgt and y in dynamic smem.
__global__ void __launch_bounds__(256) k_cmapC(){
    extern __shared__ float sm[];
    float* smT = sm;              // 32 x 257
    float* smY = sm + 32*257;     // 32 x 257 (256 used)
    int tid = threadIdx.x, blk = blockIdx.x;
    int ch = tid & 31, w = tid >> 5;
    int s  = blk*8 + w;

    for (int r=0;r<32;r++){
        int gt = blk*256 + tid;
        smT[r*257 + tid] = g_buf4[(size_t)r*T + gt];
        smY[r*257 + tid] = g_buf1[(size_t)r*T + gt];
        if (tid == 0){
            int g2 = blk*256 + 256;
            smT[r*257 + 256] = (g2 < T) ? g_buf4[(size_t)r*T + g2] : 0.f;
        }
    }
    __syncthreads();

    float aA = g_cmp[ch][0], aR = g_cmp[ch][1];
    const float K2 = 0.16609640474436813f; // log2(10)/20
    float e = g_e0[(size_t)s*32 + ch];
    int base = w*32;
    float T0 = smT[ch*257 + base];
#pragma unroll
    for (int i=0;i<SEG;i++){
        float T1 = smT[ch*257 + base + i + 1];
        float d = T0 - T1;
        e = fminf(fmaf(aA, e, d), fmaf(aR, e, d));
        float g = e + T1;
        smY[ch*257 + base + i] *= exp2f(g*K2);
        T0 = T1;
    }
    __syncthreads();

    for (int r=0;r<32;r++){
        int gt = blk*256 + tid;
        g_buf1[(size_t)r*T + gt] = smY[r*257 + tid];
    }
}

// --------------- combs: one block per (channel, comb), shuffle scan ----------
// s_t = damp*s_{t-1} + (1-damp)*w[t-L] ; w[t] = inp + fb*s_t ; out = w[t-L]
// 4-step decayed shuffle scan = exact 16-tap window (damp<=0.4 -> 4e-7);
// cross-warp seeds via unseeded warp finals (damp^32 ~ 2e-13).
__global__ void __launch_bounds__(CCH) k_comb(){
    __shared__ float ring[CR2];
    __shared__ float fin[32];
    __shared__ float carry;
    const int Lc[8] = {1116,1188,1277,1356,1422,1491,1557,1617};

    int ch = blockIdx.x & 31, k = blockIdx.x >> 5;
    int L = Lc[k];
    int tid = threadIdx.x, lane = tid & 31, w = tid >> 5;
    for (int i = tid; i < CR2; i += CCH) ring[i] = 0.f;
    if (tid == 0) carry = 0.f;
    __syncthreads();

    float fb = g_vrb[ch][0], damp = g_vrb[ch][1];
    float omd = 1.f - damp;
    float d1 = damp, d2 = d1*d1, d4 = d2*d2, d8 = d4*d4;
    float dl = powf(damp, (float)(lane+1));
    const float* __restrict__ xb = g_buf1 + (size_t)ch*T;
    float* __restrict__ co = g_cacc + ((size_t)k*NCH + ch)*T;

    for (int c = 0; c < NCC; c++){
        int t = c*CCH + tid;
        float inp = 0.015f * xb[t];
        float wv = ring[(t - L) & (CR2-1)];
        float sv = omd * wv;
        float v;
        v = __shfl_up_sync(0xFFFFFFFFu, sv, 1); if (lane >= 1) sv = fmaf(d1, v, sv);
        v = __shfl_up_sync(0xFFFFFFFFu, sv, 2); if (lane >= 2) sv = fmaf(d2, v, sv);
        v = __shfl_up_sync(0xFFFFFFFFu, sv, 4); if (lane >= 4) sv = fmaf(d4, v, sv);
        v = __shfl_up_sync(0xFFFFFFFFu, sv, 8); if (lane >= 8) sv = fmaf(d8, v, sv);
        if (lane == 31) fin[w] = sv;
        float seed0 = carry;
        co[t] = wv;
        __syncthreads();
        float seed = (w == 0) ? seed0 : fin[w-1];
        sv = fmaf(dl, seed, sv);
        ring[t & (CR2-1)] = fmaf(fb, sv, inp);
        if (tid == CCH-1) carry = sv;
        __syncthreads();
    }
}

// ----------------- allpass chain (sums 8 comb streams) + out -----------------
__global__ void __launch_bounds__(ACH) k_ap(){
    __shared__ float ring[4*ARING];
    const int La[4] = {556,441,341,225};
    int ch = blockIdx.x, tid = threadIdx.x;
    for (int i = tid; i < 4*ARING; i += ACH) ring[i] = 0.f;
    __syncthreads();

    float wet1 = g_vrb[ch][2], dryg = g_vrb[ch][3];
    const float* __restrict__ xb = g_buf1 + (size_t)ch*T;
    float* __restrict__ ob       = g_buf2 + (size_t)ch*T;

    float cur[8], curx;
#pragma unroll
    for (int k=0;k<8;k++) cur[k] = g_cacc[((size_t)k*NCH + ch)*T + tid];
    curx = xb[tid];

    for (int c = 0; c < NAC; c++){
        int t = c*ACH + tid;
        int tn = t + ACH;
        float nxt[8], nx;
#pragma unroll
        for (int k=0;k<8;k++) nxt[k] = (tn < T) ? g_cacc[((size_t)k*NCH + ch)*T + tn] : 0.f;
        nx = (tn < T) ? xb[tn] : 0.f;
        if (t < T){
            float a = ((cur[0]+cur[1])+(cur[2]+cur[3])) + ((cur[4]+cur[5])+(cur[6]+cur[7]));
#pragma unroll
            for (int k=0;k<4;k++){
                float bufv = ring[k*ARING + ((t - La[k]) & (ARING-1))];
                ring[k*ARING + (t & (ARING-1))] = fmaf(bufv, 0.5f, a);
                a = bufv - a;
            }
            ob[t] = a*wet1 + curx*dryg;
        }
#pragma unroll
        for (int k=0;k<8;k++) cur[k] = nxt[k];
        curx = nx;
        __syncthreads();
    }
}

// --------------------------------- mix -------------------------------------
__global__ void k_mix(float* __restrict__ out){
    int idx = blockIdx.x*blockDim.x + threadIdx.x;   // over 4*T
    if (idx >= 4*T) return;
    int b = idx / T, t = idx - b*T;
    float l=0.f, r=0.f;
#pragma unroll
    for (int n=0;n<8;n++){
        int ch = b*8 + n;
        float v = g_buf2[(size_t)ch*T + t];
        l = fmaf(v, g_pg[ch][0], l);
        r = fmaf(v, g_pg[ch][1], r);
    }
    out[((size_t)(b*2+0))*T + t] = l;
    out[((size_t)(b*2+1))*T + t] = r;
}

// -------------------------------- launch ------------------------------------
#define CMAPC_SM (2*32*257*4)

extern "C" void kernel_launch(void* const* d_in, const int* in_sizes, int n_in,
                              void* d_out, int out_size){
    const float* x = (const float*)d_in[0];
    const float* p = (const float*)d_in[1];
    if (n_in >= 2 && in_sizes[0] < in_sizes[1]) {
        const float* tmp = x; x = p; p = tmp;
    }
    float* out  = (float*)d_out;
    float* pout = (out_size >= 4*2*T + 4*8*24) ? out + (size_t)4*2*T : nullptr;

    static int smem_set = 0;
    if (!smem_set){
        cudaFuncSetAttribute(k_cmapC, cudaFuncAttributeMaxDynamicSharedMemorySize, CMAPC_SM);
        smem_set = 1;
    }

    k_params<<<1, 32>>>(p, pout);
    k_biquad<<<NCH, 256>>>(x);
    k_cmapA<<<NSEG/8, 256>>>();
    k_cmapB<<<1, 32>>>();
    k_cmapC<<<NSEG/8, 256, CMAPC_SM>>>();
    k_comb<<<8*NCH, CCH>>>();
    k_ap<<<NCH, ACH>>>();
    k_mix<<<(4*T + 255)/256, 256>>>(out);
}